// round 1
// baseline (speedup 1.0000x reference)
#include <cuda_runtime.h>
#include <cuda_bf16.h>
#include <cstdint>

// Problem constants
#define HD   2048
#define SEQ  2048
#define BATCH 4
#define NROWS (BATCH * SEQ)      // 8192
#define H4   (4 * HD)            // 8192
#define LN_EPS 1e-5f

// ---------------------------------------------------------------------------
// Scratch (device globals — no allocation allowed in kernel_launch)
// ---------------------------------------------------------------------------
__device__ float g_s0[(size_t)NROWS * HD];
__device__ float g_s1[(size_t)NROWS * HD];
__device__ float g_s2[(size_t)NROWS * HD];
__device__ float g_s3[(size_t)NROWS * HD];
__device__ float g_big[(size_t)NROWS * H4];   // 256 MB (silu(kk))

// ---------------------------------------------------------------------------
// LayerNorm + time-shift + two mixes.
// outA[n,c] = h*mA[c] + hh*(1-mA[c]);  outB likewise with mB.
// h = LN(x[n]); hh = LN(x[n-1]) within the same sequence, 0 at t==0.
// One block per row, 256 threads, 8 elems/thread.
// ---------------------------------------------------------------------------
__global__ __launch_bounds__(256) void ln_mix_kernel(
    const float* __restrict__ X, const float* __restrict__ gam,
    const float* __restrict__ bet, const float* __restrict__ mA,
    const float* __restrict__ mB, float* __restrict__ outA,
    float* __restrict__ outB)
{
    const int row = blockIdx.x;
    const int t   = row & (SEQ - 1);
    const int tid = threadIdx.x;
    const bool hasPrev = (t != 0);

    const float4* xr = (const float4*)(X + (size_t)row * HD);
    const float4* xp = (const float4*)(X + (size_t)(row - 1) * HD);

    float4 c[2], p[2];
    c[0] = xr[tid]; c[1] = xr[tid + 256];
    if (hasPrev) { p[0] = xp[tid]; p[1] = xp[tid + 256]; }
    else { p[0] = make_float4(0.f,0.f,0.f,0.f); p[1] = p[0]; }

    float sc = 0.f, qc = 0.f, sp = 0.f, qp = 0.f;
#pragma unroll
    for (int i = 0; i < 2; i++) {
        sc += c[i].x + c[i].y + c[i].z + c[i].w;
        qc += c[i].x*c[i].x + c[i].y*c[i].y + c[i].z*c[i].z + c[i].w*c[i].w;
        sp += p[i].x + p[i].y + p[i].z + p[i].w;
        qp += p[i].x*p[i].x + p[i].y*p[i].y + p[i].z*p[i].z + p[i].w*p[i].w;
    }
#pragma unroll
    for (int o = 16; o; o >>= 1) {
        sc += __shfl_xor_sync(0xffffffffu, sc, o);
        qc += __shfl_xor_sync(0xffffffffu, qc, o);
        sp += __shfl_xor_sync(0xffffffffu, sp, o);
        qp += __shfl_xor_sync(0xffffffffu, qp, o);
    }
    __shared__ float sm[4][8];
    __shared__ float stats[4];
    const int warp = tid >> 5, lane = tid & 31;
    if (lane == 0) { sm[0][warp]=sc; sm[1][warp]=qc; sm[2][warp]=sp; sm[3][warp]=qp; }
    __syncthreads();
    if (tid == 0) {
        float a=0.f, b2=0.f, cc=0.f, d=0.f;
#pragma unroll
        for (int i = 0; i < 8; i++) { a+=sm[0][i]; b2+=sm[1][i]; cc+=sm[2][i]; d+=sm[3][i]; }
        const float inv = 1.f / (float)HD;
        float mc = a * inv, mp = cc * inv;
        float vc = b2 * inv - mc * mc;
        float vp = d  * inv - mp * mp;
        stats[0] = mc; stats[1] = rsqrtf(vc + LN_EPS);
        stats[2] = mp; stats[3] = rsqrtf(vp + LN_EPS);
    }
    __syncthreads();
    const float mc = stats[0], rc = stats[1], mp = stats[2], rp = stats[3];

    float4* oA = (float4*)(outA + (size_t)row * HD);
    float4* oB = (float4*)(outB + (size_t)row * HD);
    const float4* g4  = (const float4*)gam;
    const float4* b4  = (const float4*)bet;
    const float4* a4  = (const float4*)mA;
    const float4* m4  = (const float4*)mB;

#pragma unroll
    for (int i = 0; i < 2; i++) {
        const int idx = tid + i * 256;
        const float4 gv = g4[idx], bv = b4[idx], av = a4[idx], mv = m4[idx];
        const float4 cv = c[i], pv = p[i];
        float4 ra, rb;
#define DO_COMP(F)                                                           \
        {                                                                    \
            float h  = (cv.F - mc) * rc * gv.F + bv.F;                       \
            float hh = hasPrev ? ((pv.F - mp) * rp * gv.F + bv.F) : 0.f;     \
            ra.F = h * av.F + hh * (1.f - av.F);                             \
            rb.F = h * mv.F + hh * (1.f - mv.F);                             \
        }
        DO_COMP(x) DO_COMP(y) DO_COMP(z) DO_COMP(w)
#undef DO_COMP
        oA[idx] = ra; oB[idx] = rb;
    }
}

// ---------------------------------------------------------------------------
// fp32 SGEMM: C[M,N] = A[M,K] * B[N,K]^T, with fused epilogues.
// 128x128 block tile, BK=8, 256 threads, 8x8 microtile, double-buffered smem.
// ---------------------------------------------------------------------------
enum { EP_NONE = 0, EP_SILU = 1, EP_SIGMUL = 2, EP_ADD = 3, EP_SIGMUL_ADD = 4 };

template <int EP>
__global__ __launch_bounds__(256, 2) void gemm_ep(
    const float* __restrict__ A, const float* __restrict__ B,
    float* __restrict__ C, const float* __restrict__ D,
    const float* __restrict__ E, int M, int N, int K)
{
    __shared__ float As[2][8][128];
    __shared__ float Bs[2][8][128];

    const int tid = threadIdx.x;
    const size_t brow = (size_t)blockIdx.y * 128;
    const size_t bcol = (size_t)blockIdx.x * 128;

    const int lm = tid >> 1;            // 0..127 (tile row)
    const int lk = (tid & 1) << 2;      // 0 or 4 (k sub-offset)
    const float* Ap = A + (brow + lm) * (size_t)K + lk;
    const float* Bp = B + (bcol + lm) * (size_t)K + lk;

    const int ty = tid >> 4;            // 0..15
    const int tx = tid & 15;            // 0..15

    float acc[8][8] = {};

    float4 av = *(const float4*)Ap;
    float4 bv = *(const float4*)Bp;
    As[0][lk+0][lm]=av.x; As[0][lk+1][lm]=av.y; As[0][lk+2][lm]=av.z; As[0][lk+3][lm]=av.w;
    Bs[0][lk+0][lm]=bv.x; Bs[0][lk+1][lm]=bv.y; Bs[0][lk+2][lm]=bv.z; Bs[0][lk+3][lm]=bv.w;
    __syncthreads();

    const int nk = K >> 3;
    for (int kt = 0; kt < nk; ++kt) {
        const int cur = kt & 1;
        if (kt + 1 < nk) {
            av = *(const float4*)(Ap + ((size_t)(kt + 1) << 3));
            bv = *(const float4*)(Bp + ((size_t)(kt + 1) << 3));
        }
#pragma unroll
        for (int kk = 0; kk < 8; ++kk) {
            float a[8], b[8];
            *(float4*)(a)     = *(const float4*)&As[cur][kk][ty * 8];
            *(float4*)(a + 4) = *(const float4*)&As[cur][kk][ty * 8 + 4];
            *(float4*)(b)     = *(const float4*)&Bs[cur][kk][tx * 8];
            *(float4*)(b + 4) = *(const float4*)&Bs[cur][kk][tx * 8 + 4];
#pragma unroll
            for (int i = 0; i < 8; i++)
#pragma unroll
                for (int j = 0; j < 8; j++)
                    acc[i][j] = fmaf(a[i], b[j], acc[i][j]);
        }
        if (kt + 1 < nk) {
            const int nx = cur ^ 1;
            As[nx][lk+0][lm]=av.x; As[nx][lk+1][lm]=av.y; As[nx][lk+2][lm]=av.z; As[nx][lk+3][lm]=av.w;
            Bs[nx][lk+0][lm]=bv.x; Bs[nx][lk+1][lm]=bv.y; Bs[nx][lk+2][lm]=bv.z; Bs[nx][lk+3][lm]=bv.w;
        }
        __syncthreads();
    }

#pragma unroll
    for (int i = 0; i < 8; i++) {
        const size_t row = brow + ty * 8 + i;
        const size_t base = row * (size_t)N + bcol + tx * 8;
#pragma unroll
        for (int j = 0; j < 8; j++) {
            const float v = acc[i][j];
            const size_t idx = base + j;
            float o;
            if (EP == EP_NONE)            o = v;
            else if (EP == EP_SILU)       o = v / (1.f + __expf(-v));
            else if (EP == EP_SIGMUL)     o = D[idx] / (1.f + __expf(-v));
            else if (EP == EP_ADD)        o = v + D[idx];
            else /* EP_SIGMUL_ADD */      o = D[idx] / (1.f + __expf(-v)) + E[idx];
            C[idx] = o;
        }
    }
}

// ---------------------------------------------------------------------------
// Launch sequence.
// Math note: wkv_run with aa=bb=0, pp=-1e38 reduces EXACTLY to wkv = v in
// fp32 (e1 underflows to 0, e2 = exp(0) = 1), so k / Wk / tm_first / tm_decay
// are dead and the Wk GEMM is skipped.
// ---------------------------------------------------------------------------
extern "C" void kernel_launch(void* const* d_in, const int* in_sizes, int n_in,
                              void* d_out, int out_size)
{
    (void)in_sizes; (void)n_in; (void)out_size;
    const float* x     = (const float*)d_in[0];
    const float* ln1_g = (const float*)d_in[1];
    const float* ln1_b = (const float*)d_in[2];
    const float* ln2_g = (const float*)d_in[3];
    const float* ln2_b = (const float*)d_in[4];
    // d_in[5] tm_decay, d_in[6] tm_first: dead (wkv == v)
    // d_in[7] tm_mk: dead (k unused)
    const float* tm_mv = (const float*)d_in[8];
    const float* tm_mr = (const float*)d_in[9];
    // d_in[10] Wk: dead
    const float* Wv    = (const float*)d_in[11];
    const float* Wr    = (const float*)d_in[12];
    const float* Wo    = (const float*)d_in[13];
    const float* cm_mk = (const float*)d_in[14];
    const float* cm_mr = (const float*)d_in[15];
    const float* Wkey  = (const float*)d_in[16];
    const float* Wval  = (const float*)d_in[17];
    const float* Wcr   = (const float*)d_in[18];
    float* out = (float*)d_out;

    float *s0, *s1, *s2, *s3, *big;
    cudaGetSymbolAddress((void**)&s0, g_s0);
    cudaGetSymbolAddress((void**)&s1, g_s1);
    cudaGetSymbolAddress((void**)&s2, g_s2);
    cudaGetSymbolAddress((void**)&s3, g_s3);
    cudaGetSymbolAddress((void**)&big, g_big);

    const dim3 blk(256);
    const dim3 gN(HD / 128, NROWS / 128);   // N = 2048
    const dim3 gW(H4 / 128, NROWS / 128);   // N = 8192

    // --- time-mix ---
    // 1) xv -> s0, xr -> s1
    ln_mix_kernel<<<NROWS, blk>>>(x, ln1_g, ln1_b, tm_mv, tm_mr, s0, s1);
    // 2) v = xv @ Wv^T -> s2
    gemm_ep<EP_NONE><<<gN, blk>>>(s0, Wv, s2, nullptr, nullptr, NROWS, HD, HD);
    // 3) u = sigmoid(xr @ Wr^T) * v -> s3
    gemm_ep<EP_SIGMUL><<<gN, blk>>>(s1, Wr, s3, s2, nullptr, NROWS, HD, HD);
    // 4) x1 = u @ Wo^T + x -> s0
    gemm_ep<EP_ADD><<<gN, blk>>>(s3, Wo, s0, x, nullptr, NROWS, HD, HD);

    // --- channel-mix ---
    // 5) xk2 -> s1, xr2 -> s2
    ln_mix_kernel<<<NROWS, blk>>>(s0, ln2_g, ln2_b, cm_mk, cm_mr, s1, s2);
    // 6) silu(xk2 @ Wkey^T) -> big   [8192 x 8192]
    gemm_ep<EP_SILU><<<gW, blk>>>(s1, Wkey, big, nullptr, nullptr, NROWS, H4, HD);
    // 7) kv = big @ Wval^T -> s3     [K = 8192]
    gemm_ep<EP_NONE><<<gN, blk>>>(big, Wval, s3, nullptr, nullptr, NROWS, HD, H4);
    // 8) out = sigmoid(xr2 @ Wcr^T) * kv + x1
    gemm_ep<EP_SIGMUL_ADD><<<gN, blk>>>(s2, Wcr, out, s3, s0, NROWS, HD, HD);
}

// round 4
// speedup vs baseline: 2.7678x; 2.7678x over previous
#include <cuda_runtime.h>
#include <cstdint>

// ---------------------------------------------------------------------------
// Problem constants
// ---------------------------------------------------------------------------
#define HD    2048
#define SEQ   2048
#define NROWS 8192            // B*T
#define H4    8192            // 4*HD
#define LN_EPS 1e-5f

// GEMM tiling: 128x128 CTA tile, K-chunk 32, 3-stage cp.async pipeline
#define NST 3
#define SPAD 36                       // smem row stride in floats (conflict-free)
#define STAGE_FLOATS (2 * 128 * SPAD) // A tile + B tile = 9216 floats
#define STAGE_BYTES  (STAGE_FLOATS * 4)         // 36864
#define SMEM_BYTES   (NST * STAGE_BYTES)        // 110592

// ---------------------------------------------------------------------------
// Scratch (device globals — no allocation allowed)
// ---------------------------------------------------------------------------
__device__ __align__(256) float g_s0[(size_t)NROWS * HD];
__device__ __align__(256) float g_s1[(size_t)NROWS * HD];
__device__ __align__(256) float g_s2[(size_t)NROWS * HD];
__device__ __align__(256) float g_s3[(size_t)NROWS * HD];
__device__ __align__(256) float g_big[(size_t)NROWS * H4];      // 256 MB
// tf32-rounded weight copies
__device__ __align__(256) float g_rWv[(size_t)HD * HD];
__device__ __align__(256) float g_rWr[(size_t)HD * HD];
__device__ __align__(256) float g_rWo[(size_t)HD * HD];
__device__ __align__(256) float g_rWcr[(size_t)HD * HD];
__device__ __align__(256) float g_rWkey[(size_t)H4 * HD];
__device__ __align__(256) float g_rWval[(size_t)HD * H4];

// ---------------------------------------------------------------------------
// Helpers
// ---------------------------------------------------------------------------
__device__ __forceinline__ uint32_t smem_u32(const void* p) {
    uint32_t a;
    asm("{ .reg .u64 t; cvta.to.shared.u64 t, %1; cvt.u32.u64 %0, t; }"
        : "=r"(a) : "l"(p));
    return a;
}

__device__ __forceinline__ float tf32r(float x) {
    uint32_t u;
    asm("cvt.rna.tf32.f32 %0, %1;" : "=r"(u) : "f"(x));
    return __uint_as_float(u);
}

#define MMA_TF32(d, a, b)                                                    \
    asm volatile(                                                            \
        "mma.sync.aligned.m16n8k8.row.col.f32.tf32.tf32.f32 "                \
        "{%0,%1,%2,%3}, {%4,%5,%6,%7}, {%8,%9}, {%0,%1,%2,%3};"              \
        : "+f"((d)[0]), "+f"((d)[1]), "+f"((d)[2]), "+f"((d)[3])             \
        : "r"((a)[0]), "r"((a)[1]), "r"((a)[2]), "r"((a)[3]),                \
          "r"((b)[0]), "r"((b)[1]))

#define CP_ASYNC16(dst, src) \
    asm volatile("cp.async.cg.shared.global [%0], [%1], 16;" :: "r"(dst), "l"(src))

// ---------------------------------------------------------------------------
// Weight rounding to tf32 (unbiased round-to-nearest)
// ---------------------------------------------------------------------------
__global__ __launch_bounds__(256) void round_w(const float4* __restrict__ in,
                                               float4* __restrict__ out, int n4) {
    int i = blockIdx.x * 256 + threadIdx.x;
    if (i < n4) {
        float4 v = in[i];
        v.x = tf32r(v.x); v.y = tf32r(v.y); v.z = tf32r(v.z); v.w = tf32r(v.w);
        out[i] = v;
    }
}

// ---------------------------------------------------------------------------
// LayerNorm + time-shift + two mixes (outputs tf32-rounded; they only feed GEMMs)
// ---------------------------------------------------------------------------
__global__ __launch_bounds__(256) void ln_mix_kernel(
    const float* __restrict__ X, const float* __restrict__ gam,
    const float* __restrict__ bet, const float* __restrict__ mA,
    const float* __restrict__ mB, float* __restrict__ outA,
    float* __restrict__ outB)
{
    const int row = blockIdx.x;
    const int t   = row & (SEQ - 1);
    const int tid = threadIdx.x;
    const bool hasPrev = (t != 0);

    const float4* xr = (const float4*)(X + (size_t)row * HD);
    const float4* xp = (const float4*)(X + (size_t)(row - 1) * HD);

    float4 c[2], p[2];
    c[0] = xr[tid]; c[1] = xr[tid + 256];
    if (hasPrev) { p[0] = xp[tid]; p[1] = xp[tid + 256]; }
    else { p[0] = make_float4(0.f,0.f,0.f,0.f); p[1] = p[0]; }

    float sc = 0.f, qc = 0.f, sp = 0.f, qp = 0.f;
#pragma unroll
    for (int i = 0; i < 2; i++) {
        sc += c[i].x + c[i].y + c[i].z + c[i].w;
        qc += c[i].x*c[i].x + c[i].y*c[i].y + c[i].z*c[i].z + c[i].w*c[i].w;
        sp += p[i].x + p[i].y + p[i].z + p[i].w;
        qp += p[i].x*p[i].x + p[i].y*p[i].y + p[i].z*p[i].z + p[i].w*p[i].w;
    }
#pragma unroll
    for (int o = 16; o; o >>= 1) {
        sc += __shfl_xor_sync(0xffffffffu, sc, o);
        qc += __shfl_xor_sync(0xffffffffu, qc, o);
        sp += __shfl_xor_sync(0xffffffffu, sp, o);
        qp += __shfl_xor_sync(0xffffffffu, qp, o);
    }
    __shared__ float sm[4][8];
    __shared__ float stats[4];
    const int warp = tid >> 5, lane = tid & 31;
    if (lane == 0) { sm[0][warp]=sc; sm[1][warp]=qc; sm[2][warp]=sp; sm[3][warp]=qp; }
    __syncthreads();
    if (tid == 0) {
        float a=0.f, b2=0.f, cc=0.f, d=0.f;
#pragma unroll
        for (int i = 0; i < 8; i++) { a+=sm[0][i]; b2+=sm[1][i]; cc+=sm[2][i]; d+=sm[3][i]; }
        const float inv = 1.f / (float)HD;
        float mc = a * inv, mp = cc * inv;
        float vc = b2 * inv - mc * mc;
        float vp = d  * inv - mp * mp;
        stats[0] = mc; stats[1] = rsqrtf(vc + LN_EPS);
        stats[2] = mp; stats[3] = rsqrtf(vp + LN_EPS);
    }
    __syncthreads();
    const float mc = stats[0], rc = stats[1], mp = stats[2], rp = stats[3];

    float4* oA = (float4*)(outA + (size_t)row * HD);
    float4* oB = (float4*)(outB + (size_t)row * HD);
    const float4* g4  = (const float4*)gam;
    const float4* b4  = (const float4*)bet;
    const float4* a4  = (const float4*)mA;
    const float4* m4  = (const float4*)mB;

#pragma unroll
    for (int i = 0; i < 2; i++) {
        const int idx = tid + i * 256;
        const float4 gv = g4[idx], bv = b4[idx], av = a4[idx], mv = m4[idx];
        const float4 cv = c[i], pv = p[i];
        float4 ra, rb;
#define DO_COMP(F)                                                           \
        {                                                                    \
            float h  = (cv.F - mc) * rc * gv.F + bv.F;                       \
            float hh = hasPrev ? ((pv.F - mp) * rp * gv.F + bv.F) : 0.f;     \
            ra.F = tf32r(h * av.F + hh * (1.f - av.F));                      \
            rb.F = tf32r(h * mv.F + hh * (1.f - mv.F));                      \
        }
        DO_COMP(x) DO_COMP(y) DO_COMP(z) DO_COMP(w)
#undef DO_COMP
        oA[idx] = ra; oB[idx] = rb;
    }
}

// ---------------------------------------------------------------------------
// tf32 mma.sync GEMM: C[M,N] = A[M,K] @ B[N,K]^T  (M = 8192 fixed)
// CTA 128x128x32, 3-stage cp.async, 8 warps (2x4), warp tile 64x32.
// Grid is 1D; tiles visited in GY=8-row groups across all N tiles so the
// B (weight) matrix stays resident in L2.
// ---------------------------------------------------------------------------
enum { EP_NONE = 0, EP_SILU = 1, EP_SIGMUL = 2, EP_ADD = 3, EP_SIGMUL_ADD = 4 };

template <int EP, bool RND>
__global__ __launch_bounds__(256, 2) void gemm_mma(
    const float* __restrict__ A, const float* __restrict__ B,
    float* __restrict__ C, const float* __restrict__ D,
    const float* __restrict__ E, int N, int K, int nn)
{
    extern __shared__ float smem[];

    const int tid  = threadIdx.x;
    const int warp = tid >> 5;
    const int lane = tid & 31;
    const int g    = lane >> 2;     // 0..7
    const int t    = lane & 3;      // 0..3
    const int wm   = warp & 1;      // 2 warps along M
    const int wn   = warp >> 1;     // 4 warps along N

    // tile mapping with GY=8 group swizzle
    const int gsz = 8 * nn;
    const int grp = blockIdx.x / gsz;
    const int rem = blockIdx.x % gsz;
    const int mt  = grp * 8 + (rem & 7);
    const int nt  = rem >> 3;
    const size_t brow = (size_t)mt * 128;
    const size_t bcol = (size_t)nt * 128;

    // cp.async assignments: each thread loads 4x16B for A and 4x16B for B
    const int lrow = tid >> 1;              // 0..127
    const int lch  = (tid & 1) * 4;         // chunk base: 0 or 4
    const float* gA = A + (brow + lrow) * (size_t)K;
    const float* gB = B + (bcol + lrow) * (size_t)K;
    const uint32_t smb = smem_u32(smem);
    const uint32_t sa_row = smb + (uint32_t)lrow * (SPAD * 4);
    const uint32_t sb_row = sa_row + 128u * (SPAD * 4);

    auto load_stage = [&](int s, int c) {
        const uint32_t so = (uint32_t)s * STAGE_BYTES;
        const float* pa = gA + (size_t)c * 32 + lch * 4;
        const float* pb = gB + (size_t)c * 32 + lch * 4;
#pragma unroll
        for (int j = 0; j < 4; j++) {
            CP_ASYNC16(sa_row + so + (uint32_t)(lch + j) * 16u, pa + j * 4);
            CP_ASYNC16(sb_row + so + (uint32_t)(lch + j) * 16u, pb + j * 4);
        }
        asm volatile("cp.async.commit_group;");
    };

    float acc[4][4][4];
#pragma unroll
    for (int i = 0; i < 4; i++)
#pragma unroll
        for (int j = 0; j < 4; j++)
#pragma unroll
            for (int r = 0; r < 4; r++) acc[i][j][r] = 0.f;

    load_stage(0, 0);
    load_stage(1, 1);

    // per-thread smem base offsets (in floats)
    const int aTb = (wm * 64 + g) * SPAD + t;
    const int bTb = (wn * 32 + g) * SPAD + t;

    const int nch = K >> 5;
    for (int c = 0; c < nch; c++) {
        const int s = c % NST;
        asm volatile("cp.async.wait_group %0;" :: "n"(NST - 2));
        __syncthreads();
        if (c + 2 < nch) load_stage((c + 2) % NST, c + 2);

        const float* sA = smem + s * STAGE_FLOATS;
        const float* sB = sA + 128 * SPAD;
#pragma unroll
        for (int ks = 0; ks < 4; ks++) {
            uint32_t af[4][4], bf[4][2];
#pragma unroll
            for (int i = 0; i < 4; i++) {
                const float* p = sA + aTb + i * (16 * SPAD) + ks * 8;
                af[i][0] = __float_as_uint(p[0]);
                af[i][1] = __float_as_uint(p[8 * SPAD]);
                af[i][2] = __float_as_uint(p[4]);
                af[i][3] = __float_as_uint(p[8 * SPAD + 4]);
            }
#pragma unroll
            for (int j = 0; j < 4; j++) {
                const float* p = sB + bTb + j * (8 * SPAD) + ks * 8;
                bf[j][0] = __float_as_uint(p[0]);
                bf[j][1] = __float_as_uint(p[4]);
            }
#pragma unroll
            for (int i = 0; i < 4; i++)
#pragma unroll
                for (int j = 0; j < 4; j++)
                    MMA_TF32(acc[i][j], af[i], bf[j]);
        }
    }
    asm volatile("cp.async.wait_group 0;");

    // ---------------- epilogue: registers -> fused ops -> STG.64 -------------
#pragma unroll
    for (int i = 0; i < 4; i++) {
#pragma unroll
        for (int j = 0; j < 4; j++) {
            const size_t row0 = brow + wm * 64 + i * 16 + g;
            const size_t col  = bcol + wn * 32 + j * 8 + 2 * t;
#pragma unroll
            for (int h = 0; h < 2; h++) {     // h=0: rows g, h=1: rows g+8
                const size_t gi = (row0 + h * 8) * (size_t)N + col;
                float v0 = acc[i][j][2 * h + 0];
                float v1 = acc[i][j][2 * h + 1];
                float2 o;
                if (EP == EP_NONE) {
                    o = make_float2(v0, v1);
                } else if (EP == EP_SILU) {
                    o = make_float2(v0 / (1.f + __expf(-v0)),
                                    v1 / (1.f + __expf(-v1)));
                } else if (EP == EP_SIGMUL) {
                    const float2 dv = *(const float2*)(D + gi);
                    o = make_float2(dv.x / (1.f + __expf(-v0)),
                                    dv.y / (1.f + __expf(-v1)));
                } else if (EP == EP_ADD) {
                    const float2 dv = *(const float2*)(D + gi);
                    o = make_float2(v0 + dv.x, v1 + dv.y);
                } else { // EP_SIGMUL_ADD
                    const float2 dv = *(const float2*)(D + gi);
                    const float2 ev = *(const float2*)(E + gi);
                    o = make_float2(dv.x / (1.f + __expf(-v0)) + ev.x,
                                    dv.y / (1.f + __expf(-v1)) + ev.y);
                }
                if (RND) { o.x = tf32r(o.x); o.y = tf32r(o.y); }
                *(float2*)(C + gi) = o;
            }
        }
    }
}

// ---------------------------------------------------------------------------
// Launch sequence.  (wkv_run with aa=bb=0, pp=-1e38 reduces exactly to wkv=v,
// so k / Wk / tm_first / tm_decay are dead and the Wk GEMM is skipped.)
// ---------------------------------------------------------------------------
extern "C" void kernel_launch(void* const* d_in, const int* in_sizes, int n_in,
                              void* d_out, int out_size)
{
    (void)in_sizes; (void)n_in; (void)out_size;
    const float* x     = (const float*)d_in[0];
    const float* ln1_g = (const float*)d_in[1];
    const float* ln1_b = (const float*)d_in[2];
    const float* ln2_g = (const float*)d_in[3];
    const float* ln2_b = (const float*)d_in[4];
    const float* tm_mv = (const float*)d_in[8];
    const float* tm_mr = (const float*)d_in[9];
    const float* Wv    = (const float*)d_in[11];
    const float* Wr    = (const float*)d_in[12];
    const float* Wo    = (const float*)d_in[13];
    const float* cm_mk = (const float*)d_in[14];
    const float* cm_mr = (const float*)d_in[15];
    const float* Wkey  = (const float*)d_in[16];
    const float* Wval  = (const float*)d_in[17];
    const float* Wcr   = (const float*)d_in[18];
    float* out = (float*)d_out;

    float *s0, *s1, *s2, *s3, *big;
    float *rWv, *rWr, *rWo, *rWcr, *rWkey, *rWval;
    cudaGetSymbolAddress((void**)&s0, g_s0);
    cudaGetSymbolAddress((void**)&s1, g_s1);
    cudaGetSymbolAddress((void**)&s2, g_s2);
    cudaGetSymbolAddress((void**)&s3, g_s3);
    cudaGetSymbolAddress((void**)&big, g_big);
    cudaGetSymbolAddress((void**)&rWv, g_rWv);
    cudaGetSymbolAddress((void**)&rWr, g_rWr);
    cudaGetSymbolAddress((void**)&rWo, g_rWo);
    cudaGetSymbolAddress((void**)&rWcr, g_rWcr);
    cudaGetSymbolAddress((void**)&rWkey, g_rWkey);
    cudaGetSymbolAddress((void**)&rWval, g_rWval);

    cudaFuncSetAttribute(gemm_mma<EP_NONE, false>,
                         cudaFuncAttributeMaxDynamicSharedMemorySize, SMEM_BYTES);
    cudaFuncSetAttribute(gemm_mma<EP_SILU, true>,
                         cudaFuncAttributeMaxDynamicSharedMemorySize, SMEM_BYTES);
    cudaFuncSetAttribute(gemm_mma<EP_SIGMUL, true>,
                         cudaFuncAttributeMaxDynamicSharedMemorySize, SMEM_BYTES);
    cudaFuncSetAttribute(gemm_mma<EP_ADD, false>,
                         cudaFuncAttributeMaxDynamicSharedMemorySize, SMEM_BYTES);
    cudaFuncSetAttribute(gemm_mma<EP_SIGMUL_ADD, false>,
                         cudaFuncAttributeMaxDynamicSharedMemorySize, SMEM_BYTES);

    // round weights to tf32 (unbiased)
    const int n4_sq = HD * HD / 4;       // 1M
    const int n4_bg = H4 * HD / 4;       // 4M
    round_w<<<n4_sq / 256, 256>>>((const float4*)Wv,   (float4*)rWv,   n4_sq);
    round_w<<<n4_sq / 256, 256>>>((const float4*)Wr,   (float4*)rWr,   n4_sq);
    round_w<<<n4_sq / 256, 256>>>((const float4*)Wo,   (float4*)rWo,   n4_sq);
    round_w<<<n4_sq / 256, 256>>>((const float4*)Wcr,  (float4*)rWcr,  n4_sq);
    round_w<<<n4_bg / 256, 256>>>((const float4*)Wkey, (float4*)rWkey, n4_bg);
    round_w<<<n4_bg / 256, 256>>>((const float4*)Wval, (float4*)rWval, n4_bg);

    const dim3 blk(256);
    const int nmT = NROWS / 128;           // 64
    const int nnSq = HD / 128;             // 16
    const int nnBg = H4 / 128;             // 64
    const dim3 gSq(nmT * nnSq);            // 1024 CTAs
    const dim3 gBg(nmT * nnBg);            // 4096 CTAs

    // --- time-mix ---
    ln_mix_kernel<<<NROWS, blk>>>(x, ln1_g, ln1_b, tm_mv, tm_mr, s0, s1);
    // v = xv @ Wv^T
    gemm_mma<EP_NONE, false><<<gSq, blk, SMEM_BYTES>>>(s0, rWv, s2, nullptr, nullptr, HD, HD, nnSq);
    // u = sigmoid(xr @ Wr^T) * v   (rounded; feeds Wo GEMM)
    gemm_mma<EP_SIGMUL, true><<<gSq, blk, SMEM_BYTES>>>(s1, rWr, s3, s2, nullptr, HD, HD, nnSq);
    // x1 = u @ Wo^T + x
    gemm_mma<EP_ADD, false><<<gSq, blk, SMEM_BYTES>>>(s3, rWo, s0, x, nullptr, HD, HD, nnSq);

    // --- channel-mix ---
    ln_mix_kernel<<<NROWS, blk>>>(s0, ln2_g, ln2_b, cm_mk, cm_mr, s1, s2);
    // silu(xk2 @ Wkey^T)  (rounded; feeds Wval GEMM)
    gemm_mma<EP_SILU, true><<<gBg, blk, SMEM_BYTES>>>(s1, rWkey, big, nullptr, nullptr, H4, HD, nnBg);
    // kv = big @ Wval^T
    gemm_mma<EP_NONE, false><<<gSq, blk, SMEM_BYTES>>>(big, rWval, s3, nullptr, nullptr, HD, H4, nnSq);
    // out = sigmoid(xr2 @ Wcr^T) * kv + x1
    gemm_mma<EP_SIGMUL_ADD, false><<<gSq, blk, SMEM_BYTES>>>(s2, rWcr, out, s3, s0, HD, HD, nnSq);
}